// round 11
// baseline (speedup 1.0000x reference)
#include <cuda_runtime.h>
#include <cuda_bf16.h>
#include <math.h>
#include <stdint.h>

// Problem constants
#define BB      2
#define TT      2048
#define DD      2048
#define HH      256
#define BT      (BB*TT)        // 4096 rows
#define NHEADS  4
#define HD      64
#define WINR    15
#define EPSV    1e-5f

// ---------------- scratch (device globals; allocation-free) ----------------
__device__ float g_h0[BT*HH];
__device__ float g_h1[BT*HH];
__device__ float g_hW[BT*HH];
__device__ __nv_bfloat16 g_Wpt_hi[HH*DD];
__device__ __nv_bfloat16 g_Wpt_lo[HH*DD];
__device__ __nv_bfloat16 g_W0t_hi[HH*HH];
__device__ __nv_bfloat16 g_W0t_lo[HH*HH];
__device__ __nv_bfloat16 g_W1t_hi[HH*HH];
__device__ __nv_bfloat16 g_W1t_lo[HH*HH];

// ---------------- helpers ----------------
__device__ __forceinline__ uint32_t smem_u32(const void* p) {
    uint32_t a;
    asm("{ .reg .u64 t; cvta.to.shared.u64 t, %1; cvt.u32.u64 %0, t; }"
        : "=r"(a) : "l"(p));
    return a;
}
__device__ __forceinline__ uint32_t swz(uint32_t off) {   // SW128 XOR swizzle
    return off ^ ((off >> 3) & 0x70);
}
__device__ __forceinline__ void ldm_x4(uint32_t& r0, uint32_t& r1, uint32_t& r2,
                                       uint32_t& r3, uint32_t addr) {
    asm volatile("ldmatrix.sync.aligned.m8n8.x4.shared.b16 {%0,%1,%2,%3}, [%4];"
                 : "=r"(r0), "=r"(r1), "=r"(r2), "=r"(r3) : "r"(addr));
}
__device__ __forceinline__ void mma_bf16(float* d, const uint32_t* a, const uint32_t* b) {
    asm volatile(
        "mma.sync.aligned.m16n8k16.row.col.f32.bf16.bf16.f32 "
        "{%0,%1,%2,%3}, {%4,%5,%6,%7}, {%8,%9}, {%0,%1,%2,%3};"
        : "+f"(d[0]), "+f"(d[1]), "+f"(d[2]), "+f"(d[3])
        : "r"(a[0]), "r"(a[1]), "r"(a[2]), "r"(a[3]), "r"(b[0]), "r"(b[1]));
}
__device__ __forceinline__ uint32_t pack_bf16(float x, float y) {
    __nv_bfloat162 p(__float2bfloat16(x), __float2bfloat16(y));
    return *reinterpret_cast<uint32_t*>(&p);
}
__device__ __forceinline__ void cp_async16(uint32_t dst, const void* src) {
    asm volatile("cp.async.cg.shared.global [%0], [%1], 16;"
                 :: "r"(dst), "l"(src) : "memory");
}
__device__ __forceinline__ void cp_commit() {
    asm volatile("cp.async.commit_group;" ::: "memory");
}
__device__ __forceinline__ void cp_wait0() {
    asm volatile("cp.async.wait_group 0;" ::: "memory");
}

// ---------------------------------------------------------------------------
// Weight prep: smem-tiled transpose + bf16 split (32x32 tiles).
// ---------------------------------------------------------------------------
__global__ __launch_bounds__(256) void wprep_tiled_kernel(
    const float* __restrict__ Wp, __nv_bfloat16* __restrict__ Wph, __nv_bfloat16* __restrict__ Wpl,
    const float* __restrict__ W0, __nv_bfloat16* __restrict__ W0h, __nv_bfloat16* __restrict__ W0l,
    const float* __restrict__ W1, __nv_bfloat16* __restrict__ W1h, __nv_bfloat16* __restrict__ W1l)
{
    int blk = blockIdx.x;
    const float* W; __nv_bfloat16 *Wh, *Wl; int K, N;
    if (blk < 512)      { W = Wp; Wh = Wph; Wl = Wpl; K = DD; N = HH; }
    else if (blk < 576) { W = W0; Wh = W0h; Wl = W0l; K = HH; N = HH; blk -= 512; }
    else                { W = W1; Wh = W1h; Wl = W1l; K = HH; N = HH; blk -= 576; }
    const int tpr = N / 32;
    const int tk = blk / tpr, tn = blk - tk * tpr;

    __shared__ float ts[32][33];
    const int r = threadIdx.x >> 5, c = threadIdx.x & 31;
#pragma unroll
    for (int i = 0; i < 4; i++)
        ts[r + i * 8][c] = W[(size_t)(tk * 32 + r + i * 8) * N + tn * 32 + c];
    __syncthreads();
#pragma unroll
    for (int i = 0; i < 4; i++) {
        int nn = tn * 32 + r + i * 8;
        float v = ts[c][r + i * 8];
        __nv_bfloat16 hi = __float2bfloat16(v);
        __nv_bfloat16 lo = __float2bfloat16(v - __bfloat162float(hi));
        size_t o = (size_t)nn * K + tk * 32 + c;
        Wh[o] = hi;
        Wl[o] = lo;
    }
}

// ---------------------------------------------------------------------------
// Projection GEMM 128x64, BK=32, double-buffered, split-K via gridDim.z.
// ---------------------------------------------------------------------------
#define GBM 128
#define GBN 64
#define GBK 32

template<int NSPLIT>
__global__ __launch_bounds__(256) void gemm_mma_kernel(
    const float* __restrict__ A, const __nv_bfloat16* __restrict__ Bhi,
    const __nv_bfloat16* __restrict__ Blo, const float* __restrict__ bias,
    float* __restrict__ C0, float* __restrict__ C1, int K)
{
    __shared__ __align__(1024) uint8_t sA[2][GBM * 128];
    __shared__ __align__(1024) uint8_t sB[2][GBN * 128];
    const uint32_t sAb0 = smem_u32(sA[0]), sAb1 = smem_u32(sA[1]);
    const uint32_t sBb0 = smem_u32(sB[0]), sBb1 = smem_u32(sB[1]);

    const int tid = threadIdx.x, wid = tid >> 5, lane = tid & 31;
    const int row0 = blockIdx.y * GBM;
    const int n0   = blockIdx.x * GBN;
    const int ksec  = K / NSPLIT;
    const int kbase = (NSPLIT > 1) ? blockIdx.z * ksec : 0;
    float* __restrict__ C = (NSPLIT > 1 && blockIdx.z == 1) ? C1 : C0;
    const int warpM = (wid >> 1) * 32;
    const int warpN = (wid & 1) * 32;

    float d[2][4][4];
#pragma unroll
    for (int mt = 0; mt < 2; mt++)
#pragma unroll
        for (int nt = 0; nt < 4; nt++)
#pragma unroll
            for (int i = 0; i < 4; i++) d[mt][nt][i] = 0.f;

    const int bn = tid >> 2, bq = tid & 3;
    const int NIT = ksec / GBK;
    float4 aR[4];

    auto ldgA = [&](int it) {
        const int k0 = kbase + it * GBK;
#pragma unroll
        for (int i = 0; i < 4; i++) {
            int slot = tid + i * 256;
            int r = slot >> 3, c = slot & 7;
            aR[i] = *reinterpret_cast<const float4*>(
                &A[(size_t)(row0 + r) * K + k0 + c * 4]);
        }
    };
    auto cpB = [&](int it, uint32_t sBb) {
        const int k0 = kbase + it * GBK;
        cp_async16(sBb + swz((uint32_t)(bn * 128 + bq * 16)),
                   &Bhi[(size_t)(n0 + bn) * K + k0 + bq * 8]);
        cp_async16(sBb + swz((uint32_t)(bn * 128 + 64 + bq * 16)),
                   &Blo[(size_t)(n0 + bn) * K + k0 + bq * 8]);
        cp_commit();
    };
    auto stsA = [&](uint8_t* dst) {
#pragma unroll
        for (int i = 0; i < 4; i++) {
            int slot = tid + i * 256;
            int r = slot >> 3, c = slot & 7;
            float4 v = aR[i];
            uint32_t h0 = pack_bf16(v.x, v.y), h1 = pack_bf16(v.z, v.w);
            float rx = v.x - __bfloat162float(__float2bfloat16(v.x));
            float ry = v.y - __bfloat162float(__float2bfloat16(v.y));
            float rz = v.z - __bfloat162float(__float2bfloat16(v.z));
            float rw = v.w - __bfloat162float(__float2bfloat16(v.w));
            uint32_t l0 = pack_bf16(rx, ry), l1 = pack_bf16(rz, rw);
            *reinterpret_cast<uint2*>(dst + swz((uint32_t)(r * 128 + c * 8)))
                = make_uint2(h0, h1);
            *reinterpret_cast<uint2*>(dst + swz((uint32_t)(r * 128 + 64 + c * 8)))
                = make_uint2(l0, l1);
        }
    };

    ldgA(0);
    cpB(0, sBb0);
    stsA(sA[0]);
    if (NIT > 1) ldgA(1);
    cp_wait0();
    __syncthreads();

    for (int it = 0; it < NIT; ++it) {
        const int s = it & 1;
        const uint32_t sAb = s ? sAb1 : sAb0;
        const uint32_t sBb = s ? sBb1 : sBb0;

        if (it + 1 < NIT) {
            cpB(it + 1, s ? sBb0 : sBb1);
            stsA(s ? sA[0] : sA[1]);
            if (it + 2 < NIT) ldgA(it + 2);
        }

#pragma unroll
        for (int kk = 0; kk < 2; kk++) {
            uint32_t ahi[2][4], alo[2][4], bhi[4][2], blo[4][2];
#pragma unroll
            for (int mt = 0; mt < 2; mt++) {
                int mrow = warpM + mt * 16 + (lane & 15);
                uint32_t kbyte = (uint32_t)((kk * 16 + ((lane >> 4) << 3)) * 2);
                ldm_x4(ahi[mt][0], ahi[mt][1], ahi[mt][2], ahi[mt][3],
                       sAb + swz((uint32_t)(mrow * 128) + kbyte));
                ldm_x4(alo[mt][0], alo[mt][1], alo[mt][2], alo[mt][3],
                       sAb + swz((uint32_t)(mrow * 128) + 64u + kbyte));
            }
#pragma unroll
            for (int p = 0; p < 2; p++) {
                int sel = lane >> 3, l8 = lane & 7;
                int nrow = warpN + p * 16 + ((sel & 2) ? 8 : 0) + l8;
                uint32_t kbyte = (uint32_t)((kk * 16 + (sel & 1) * 8) * 2);
                uint32_t q0, q1, q2, q3;
                ldm_x4(q0, q1, q2, q3, sBb + swz((uint32_t)(nrow * 128) + kbyte));
                bhi[p * 2 + 0][0] = q0; bhi[p * 2 + 0][1] = q1;
                bhi[p * 2 + 1][0] = q2; bhi[p * 2 + 1][1] = q3;
                ldm_x4(q0, q1, q2, q3, sBb + swz((uint32_t)(nrow * 128) + 64u + kbyte));
                blo[p * 2 + 0][0] = q0; blo[p * 2 + 0][1] = q1;
                blo[p * 2 + 1][0] = q2; blo[p * 2 + 1][1] = q3;
            }
#pragma unroll
            for (int mt = 0; mt < 2; mt++)
#pragma unroll
                for (int nt = 0; nt < 4; nt++) {
                    mma_bf16(d[mt][nt], ahi[mt], bhi[nt]);
                    mma_bf16(d[mt][nt], alo[mt], bhi[nt]);
                    mma_bf16(d[mt][nt], ahi[mt], blo[nt]);
                }
        }

        if (it + 1 < NIT) cp_wait0();
        __syncthreads();
    }

    const int rq = lane >> 2, cq = (lane & 3) * 2;
#pragma unroll
    for (int mt = 0; mt < 2; mt++)
#pragma unroll
        for (int nt = 0; nt < 4; nt++) {
            int row = row0 + warpM + mt * 16 + rq;
            int col = n0 + warpN + nt * 8 + cq;
            float b0 = 0.f, b1 = 0.f;
            if (NSPLIT == 1 && bias) { b0 = bias[col]; b1 = bias[col + 1]; }
            *reinterpret_cast<float2*>(&C[(size_t)row * HH + col]) =
                make_float2(d[mt][nt][0] + b0, d[mt][nt][1] + b1);
            *reinterpret_cast<float2*>(&C[(size_t)(row + 8) * HH + col]) =
                make_float2(d[mt][nt][2] + b0, d[mt][nt][3] + b1);
        }
}

// ---------------------------------------------------------------------------
// Small GEMM (K=256): fully smem-resident, barrier-free mainloop.
// CTA tile 64x64; A+B hi/lo all staged (128 KB dynamic smem), ONE sync,
// then 8 chunks x 2 k16 of ldsm+mma with no barriers. Grid 256 CTAs.
// Smem layout: A chunk ck at ck*8192 (64 rows x 128B: hi|lo), B at 65536+ck*8192.
// ---------------------------------------------------------------------------
#define SG_SMEM 131072

__global__ __launch_bounds__(256) void gemm_small_kernel(
    const float* __restrict__ A, const __nv_bfloat16* __restrict__ Bhi,
    const __nv_bfloat16* __restrict__ Blo, float* __restrict__ C)
{
    extern __shared__ __align__(1024) uint8_t smem[];
    const uint32_t sAb = smem_u32(smem);
    const uint32_t sBb = sAb + 65536;

    const int tid = threadIdx.x, wid = tid >> 5, lane = tid & 31;
    const int row0 = blockIdx.y * 64;
    const int n0   = blockIdx.x * 64;
    const int warpM = (wid >> 1) * 16;
    const int warpN = (wid & 1) * 32;

    // ---- fill B: 8 chunks via cp.async ----
    {
        const int bn = tid >> 2, bq = tid & 3;
#pragma unroll
        for (int ck = 0; ck < 8; ck++) {
            uint32_t sBc = sBb + ck * 8192;
            cp_async16(sBc + swz((uint32_t)(bn * 128 + bq * 16)),
                       &Bhi[(size_t)(n0 + bn) * HH + ck * 32 + bq * 8]);
            cp_async16(sBc + swz((uint32_t)(bn * 128 + 64 + bq * 16)),
                       &Blo[(size_t)(n0 + bn) * HH + ck * 32 + bq * 8]);
        }
        cp_commit();
    }
    // ---- fill A: 16 float4 per thread, convert to hi/lo ----
#pragma unroll
    for (int i = 0; i < 16; i++) {
        int slot = tid + i * 256;
        int r = slot >> 6, c = slot & 63;      // c = float4 column (K/4)
        float4 v = *reinterpret_cast<const float4*>(
            &A[(size_t)(row0 + r) * HH + c * 4]);
        int ck = c >> 3, c4 = c & 7;
        uint8_t* dst = smem + ck * 8192;
        uint32_t h0 = pack_bf16(v.x, v.y), h1 = pack_bf16(v.z, v.w);
        float rx = v.x - __bfloat162float(__float2bfloat16(v.x));
        float ry = v.y - __bfloat162float(__float2bfloat16(v.y));
        float rz = v.z - __bfloat162float(__float2bfloat16(v.z));
        float rw = v.w - __bfloat162float(__float2bfloat16(v.w));
        uint32_t l0 = pack_bf16(rx, ry), l1 = pack_bf16(rz, rw);
        *reinterpret_cast<uint2*>(dst + swz((uint32_t)(r * 128 + c4 * 8)))
            = make_uint2(h0, h1);
        *reinterpret_cast<uint2*>(dst + swz((uint32_t)(r * 128 + 64 + c4 * 8)))
            = make_uint2(l0, l1);
    }
    cp_wait0();
    __syncthreads();

    float d[4][4];
#pragma unroll
    for (int nt = 0; nt < 4; nt++)
#pragma unroll
        for (int i = 0; i < 4; i++) d[nt][i] = 0.f;

    // ---- barrier-free mainloop: 8 chunks x 2 k16 ----
#pragma unroll
    for (int ck = 0; ck < 8; ck++) {
        const uint32_t sAc = sAb + ck * 8192;
        const uint32_t sBc = sBb + ck * 8192;
#pragma unroll
        for (int kk = 0; kk < 2; kk++) {
            uint32_t ahi[4], alo[4], bhi[4][2], blo[4][2];
            {
                int mrow = warpM + (lane & 15);
                uint32_t kbyte = (uint32_t)((kk * 16 + ((lane >> 4) << 3)) * 2);
                ldm_x4(ahi[0], ahi[1], ahi[2], ahi[3],
                       sAc + swz((uint32_t)(mrow * 128) + kbyte));
                ldm_x4(alo[0], alo[1], alo[2], alo[3],
                       sAc + swz((uint32_t)(mrow * 128) + 64u + kbyte));
            }
#pragma unroll
            for (int p = 0; p < 2; p++) {
                int sel = lane >> 3, l8 = lane & 7;
                int nrow = warpN + p * 16 + ((sel & 2) ? 8 : 0) + l8;
                uint32_t kbyte = (uint32_t)((kk * 16 + (sel & 1) * 8) * 2);
                uint32_t q0, q1, q2, q3;
                ldm_x4(q0, q1, q2, q3, sBc + swz((uint32_t)(nrow * 128) + kbyte));
                bhi[p * 2 + 0][0] = q0; bhi[p * 2 + 0][1] = q1;
                bhi[p * 2 + 1][0] = q2; bhi[p * 2 + 1][1] = q3;
                ldm_x4(q0, q1, q2, q3, sBc + swz((uint32_t)(nrow * 128) + 64u + kbyte));
                blo[p * 2 + 0][0] = q0; blo[p * 2 + 0][1] = q1;
                blo[p * 2 + 1][0] = q2; blo[p * 2 + 1][1] = q3;
            }
#pragma unroll
            for (int nt = 0; nt < 4; nt++) {
                mma_bf16(d[nt], ahi, bhi[nt]);
                mma_bf16(d[nt], alo, bhi[nt]);
                mma_bf16(d[nt], ahi, blo[nt]);
            }
        }
    }

    const int rq = lane >> 2, cq = (lane & 3) * 2;
#pragma unroll
    for (int nt = 0; nt < 4; nt++) {
        int row = row0 + warpM + rq;
        int col = n0 + warpN + nt * 8 + cq;
        *reinterpret_cast<float2*>(&C[(size_t)row * HH + col]) =
            make_float2(d[nt][0], d[nt][1]);
        *reinterpret_cast<float2*>(&C[(size_t)(row + 8) * HH + col]) =
            make_float2(d[nt][2], d[nt][3]);
    }
}

// ---------------------------------------------------------------------------
// Split-K reduction: C = P0 + P1 + bias
// ---------------------------------------------------------------------------
__global__ __launch_bounds__(256) void addbias_kernel(
    const float* __restrict__ P0, const float* __restrict__ P1,
    const float* __restrict__ bias, float* __restrict__ C)
{
    int i = blockIdx.x * 256 + threadIdx.x;
    int col = (i * 4) & (HH - 1);
    float4 a = *reinterpret_cast<const float4*>(&P0[(size_t)i * 4]);
    float4 b = *reinterpret_cast<const float4*>(&P1[(size_t)i * 4]);
    float4 bv = *reinterpret_cast<const float4*>(&bias[col]);
    *reinterpret_cast<float4*>(&C[(size_t)i * 4]) =
        make_float4(a.x + b.x + bv.x, a.y + b.y + bv.y,
                    a.z + b.z + bv.z, a.w + b.w + bv.w);
}

// ---------------------------------------------------------------------------
// Fused attention: RPB=16, zero-padded tile, JOINT 2-row register aggregation
// (each tile row loaded once, feeds both rows), + residual + LN (+ final LN).
// ---------------------------------------------------------------------------
#define RPB   16
#define NTROW (RPB + 2*WINR)              // 46
#define NJ    (2*WINR + 1)                // 31
#define WST   33
#define AT_TILE 0
#define AT_ES   47104
#define AT_ED   47872
#define AT_SA   48640
#define AT_SD   49664
#define AT_W    50688
#define ATTN_SMEM 59136

template<bool FINAL_LN>
__global__ __launch_bounds__(256, 2) void attn_fused_kernel(
    const float* __restrict__ h,  const float* __restrict__ hW,
    const float* __restrict__ asrc, const float* __restrict__ adst,
    const float* __restrict__ g,  const float* __restrict__ b,
    const float* __restrict__ gF, const float* __restrict__ bF,
    float* __restrict__ out)
{
    extern __shared__ char sm[];
    float* tile = (float*)(sm + AT_TILE);
    float* es_s = (float*)(sm + AT_ES);
    float* ed_s = (float*)(sm + AT_ED);
    float* sa   = (float*)(sm + AT_SA);
    float* sd   = (float*)(sm + AT_SD);
    float* wsm  = (float*)(sm + AT_W);

    const int tid = threadIdx.x, wid = tid >> 5, lane = tid & 31;
    const int bpb = TT / RPB;
    const int batch = blockIdx.x / bpb;
    const int t0 = (blockIdx.x - batch * bpb) * RPB;
    const int gbase = batch * TT;

    for (int idx = tid; idx < NTROW * 64; idx += 256) {
        int r = idx >> 6, c4 = idx & 63;
        int tg = t0 - WINR + r;
        float4 v = make_float4(0.f, 0.f, 0.f, 0.f);
        if (tg >= 0 && tg < TT)
            v = *reinterpret_cast<const float4*>(
                &hW[(size_t)(gbase + tg) * HH + c4 * 4]);
        *reinterpret_cast<float4*>(&tile[r * 256 + c4 * 4]) = v;
    }
    sa[tid] = asrc[tid];
    sd[tid] = adst[tid];
    __syncthreads();

    {
        const int head = lane >> 3, dk = lane & 7;
        const int base4 = head * 16 + dk * 2;
        float4 s0 = *reinterpret_cast<float4*>(&sa[base4 * 4]);
        float4 s1 = *reinterpret_cast<float4*>(&sa[base4 * 4 + 4]);
        float4 dd0 = *reinterpret_cast<float4*>(&sd[base4 * 4]);
        float4 dd1 = *reinterpret_cast<float4*>(&sd[base4 * 4 + 4]);
        for (int r = wid; r < NTROW; r += 8) {
            float4 v0 = *reinterpret_cast<float4*>(&tile[r * 256 + base4 * 4]);
            float4 v1 = *reinterpret_cast<float4*>(&tile[r * 256 + base4 * 4 + 4]);
            float ps = v0.x*s0.x + v0.y*s0.y + v0.z*s0.z + v0.w*s0.w
                     + v1.x*s1.x + v1.y*s1.y + v1.z*s1.z + v1.w*s1.w;
            float pd = v0.x*dd0.x + v0.y*dd0.y + v0.z*dd0.z + v0.w*dd0.w
                     + v1.x*dd1.x + v1.y*dd1.y + v1.z*dd1.z + v1.w*dd1.w;
#pragma unroll
            for (int o = 4; o > 0; o >>= 1) {
                ps += __shfl_xor_sync(0xffffffffu, ps, o);
                pd += __shfl_xor_sync(0xffffffffu, pd, o);
            }
            if (dk == 0) { es_s[r * 4 + head] = ps; ed_s[r * 4 + head] = pd; }
        }
    }
    __syncthreads();

#pragma unroll
    for (int q = 0; q < 8; q++) {
        int p = wid + 8 * q;
        int r = p >> 2, head = p & 3;
        int t = t0 + r;
        int tn = t - WINR + lane;
        bool valid = (lane < NJ) && (tn >= 0) && (tn < TT);
        float e = -1e30f;
        if (valid) {
            float v = es_s[(r + WINR) * 4 + head] + ed_s[(r + lane) * 4 + head];
            e = (v > 0.f) ? v : 0.2f * v;
        }
        float m = e;
#pragma unroll
        for (int o = 16; o > 0; o >>= 1) m = fmaxf(m, __shfl_xor_sync(0xffffffffu, m, o));
        float xv = valid ? __expf(e - m) : 0.f;
        float s = xv;
#pragma unroll
        for (int o = 16; o > 0; o >>= 1) s += __shfl_xor_sync(0xffffffffu, s, o);
        wsm[p * WST + lane] = xv / s;    // lane 31 stores exactly 0
    }
    __syncthreads();

    // --- joint 2-row aggregation: rows r0=2*wid, r0+1 share tile rows ---
    const int c0 = lane * 8;
    const int head = lane >> 3;
    const int r0 = wid * 2;
    const float* w0 = &wsm[(r0 * 4 + head) * WST];
    const float* w1 = &wsm[((r0 + 1) * 4 + head) * WST];
    float a0[8], a1[8];
#pragma unroll
    for (int k = 0; k < 8; k++) { a0[k] = 0.f; a1[k] = 0.f; }
#pragma unroll
    for (int u = 0; u < 32; u++) {
        const float* trow = &tile[(r0 + u) * 256 + c0];
        float4 t0v = *reinterpret_cast<const float4*>(trow);
        float4 t1v = *reinterpret_cast<const float4*>(trow + 4);
        float wa = w0[u];                         // w0[31] == 0
        float wb = (u == 0) ? 0.f : w1[u - 1];
        a0[0] = fmaf(wa, t0v.x, a0[0]); a0[1] = fmaf(wa, t0v.y, a0[1]);
        a0[2] = fmaf(wa, t0v.z, a0[2]); a0[3] = fmaf(wa, t0v.w, a0[3]);
        a0[4] = fmaf(wa, t1v.x, a0[4]); a0[5] = fmaf(wa, t1v.y, a0[5]);
        a0[6] = fmaf(wa, t1v.z, a0[6]); a0[7] = fmaf(wa, t1v.w, a0[7]);
        a1[0] = fmaf(wb, t0v.x, a1[0]); a1[1] = fmaf(wb, t0v.y, a1[1]);
        a1[2] = fmaf(wb, t0v.z, a1[2]); a1[3] = fmaf(wb, t0v.w, a1[3]);
        a1[4] = fmaf(wb, t1v.x, a1[4]); a1[5] = fmaf(wb, t1v.y, a1[5]);
        a1[6] = fmaf(wb, t1v.z, a1[6]); a1[7] = fmaf(wb, t1v.w, a1[7]);
    }

    // --- per-row residual + LN (+ final LN) + store ---
#pragma unroll
    for (int rr = 0; rr < 2; rr++) {
        float* a = rr ? a1 : a0;
        const int r = r0 + rr;
        const size_t grow = (size_t)(gbase + t0 + r) * HH;
        float4 h0v = *reinterpret_cast<const float4*>(&h[grow + c0]);
        float4 h1v = *reinterpret_cast<const float4*>(&h[grow + c0 + 4]);
        a[0] += h0v.x; a[1] += h0v.y; a[2] += h0v.z; a[3] += h0v.w;
        a[4] += h1v.x; a[5] += h1v.y; a[6] += h1v.z; a[7] += h1v.w;
        float s1 = 0.f, s2 = 0.f;
#pragma unroll
        for (int k = 0; k < 8; k++) { s1 += a[k]; s2 += a[k] * a[k]; }
#pragma unroll
        for (int o = 16; o > 0; o >>= 1) {
            s1 += __shfl_xor_sync(0xffffffffu, s1, o);
            s2 += __shfl_xor_sync(0xffffffffu, s2, o);
        }
        float mu  = s1 * (1.f / 256.f);
        float var = s2 * (1.f / 256.f) - mu * mu;
        float inv = rsqrtf(var + EPSV);
        float4 g0v = *reinterpret_cast<const float4*>(&g[c0]);
        float4 g1v = *reinterpret_cast<const float4*>(&g[c0 + 4]);
        float4 b0v = *reinterpret_cast<const float4*>(&b[c0]);
        float4 b1v = *reinterpret_cast<const float4*>(&b[c0 + 4]);
        float z[8];
        z[0] = (a[0]-mu)*inv*g0v.x + b0v.x; z[1] = (a[1]-mu)*inv*g0v.y + b0v.y;
        z[2] = (a[2]-mu)*inv*g0v.z + b0v.z; z[3] = (a[3]-mu)*inv*g0v.w + b0v.w;
        z[4] = (a[4]-mu)*inv*g1v.x + b1v.x; z[5] = (a[5]-mu)*inv*g1v.y + b1v.y;
        z[6] = (a[6]-mu)*inv*g1v.z + b1v.z; z[7] = (a[7]-mu)*inv*g1v.w + b1v.w;
        if (FINAL_LN) {
            float z1 = 0.f, z2 = 0.f;
#pragma unroll
            for (int k = 0; k < 8; k++) { z1 += z[k]; z2 += z[k] * z[k]; }
#pragma unroll
            for (int o = 16; o > 0; o >>= 1) {
                z1 += __shfl_xor_sync(0xffffffffu, z1, o);
                z2 += __shfl_xor_sync(0xffffffffu, z2, o);
            }
            float mu2  = z1 * (1.f / 256.f);
            float var2 = z2 * (1.f / 256.f) - mu2 * mu2;
            float inv2 = rsqrtf(var2 + EPSV);
            float4 gf0 = *reinterpret_cast<const float4*>(&gF[c0]);
            float4 gf1 = *reinterpret_cast<const float4*>(&gF[c0 + 4]);
            float4 bf0 = *reinterpret_cast<const float4*>(&bF[c0]);
            float4 bf1 = *reinterpret_cast<const float4*>(&bF[c0 + 4]);
            z[0] = (z[0]-mu2)*inv2*gf0.x + bf0.x; z[1] = (z[1]-mu2)*inv2*gf0.y + bf0.y;
            z[2] = (z[2]-mu2)*inv2*gf0.z + bf0.z; z[3] = (z[3]-mu2)*inv2*gf0.w + bf0.w;
            z[4] = (z[4]-mu2)*inv2*gf1.x + bf1.x; z[5] = (z[5]-mu2)*inv2*gf1.y + bf1.y;
            z[6] = (z[6]-mu2)*inv2*gf1.z + bf1.z; z[7] = (z[7]-mu2)*inv2*gf1.w + bf1.w;
        }
        *reinterpret_cast<float4*>(&out[grow + c0]) =
            make_float4(z[0], z[1], z[2], z[3]);
        *reinterpret_cast<float4*>(&out[grow + c0 + 4]) =
            make_float4(z[4], z[5], z[6], z[7]);
    }
}

// ---------------------------------------------------------------------------
extern "C" void kernel_launch(void* const* d_in, const int* in_sizes, int n_in,
                              void* d_out, int out_size)
{
    const float* x     = (const float*)d_in[0];
    // d_in[1] = adj_mask (banded window reconstructed analytically; unused)
    const float* Wp    = (const float*)d_in[2];
    const float* bp    = (const float*)d_in[3];
    const float* W0    = (const float*)d_in[4];
    const float* asrc0 = (const float*)d_in[5];
    const float* adst0 = (const float*)d_in[6];
    const float* g0    = (const float*)d_in[7];
    const float* b0    = (const float*)d_in[8];
    const float* W1    = (const float*)d_in[9];
    const float* asrc1 = (const float*)d_in[10];
    const float* adst1 = (const float*)d_in[11];
    const float* g1    = (const float*)d_in[12];
    const float* b1    = (const float*)d_in[13];
    const float* gF    = (const float*)d_in[14];
    const float* bF    = (const float*)d_in[15];
    float* out = (float*)d_out;

    float *h0, *h1, *hW;
    __nv_bfloat16 *Wpth, *Wptl, *W0th, *W0tl, *W1th, *W1tl;
    cudaGetSymbolAddress((void**)&h0, g_h0);
    cudaGetSymbolAddress((void**)&h1, g_h1);
    cudaGetSymbolAddress((void**)&hW, g_hW);
    cudaGetSymbolAddress((void**)&Wpth, g_Wpt_hi);
    cudaGetSymbolAddress((void**)&Wptl, g_Wpt_lo);
    cudaGetSymbolAddress((void**)&W0th, g_W0t_hi);
    cudaGetSymbolAddress((void**)&W0tl, g_W0t_lo);
    cudaGetSymbolAddress((void**)&W1th, g_W1t_hi);
    cudaGetSymbolAddress((void**)&W1tl, g_W1t_lo);

    cudaFuncSetAttribute(attn_fused_kernel<false>,
        cudaFuncAttributeMaxDynamicSharedMemorySize, ATTN_SMEM);
    cudaFuncSetAttribute(attn_fused_kernel<true>,
        cudaFuncAttributeMaxDynamicSharedMemorySize, ATTN_SMEM);
    cudaFuncSetAttribute(gemm_small_kernel,
        cudaFuncAttributeMaxDynamicSharedMemorySize, SG_SMEM);

    // Weight prep: tiled transpose, 640 blocks
    wprep_tiled_kernel<<<640, 256>>>(
        Wp, Wpth, Wptl, W0, W0th, W0tl, W1, W1th, W1tl);

    // ---- projection: split-K=2 partials + reduce ----
    dim3 gProj(HH / GBN, BT / GBM, 2);      // (4, 32, 2) = 256 CTAs
    gemm_mma_kernel<2><<<gProj, 256>>>(x, Wpth, Wptl, nullptr, h1, hW, DD);
    addbias_kernel<<<(BT * HH / 4) / 256, 256>>>(h1, hW, bp, h0);

    dim3 gg64(HH / 64, BT / 64);            // (4, 64) = 256 CTAs

    // --- GAT block 0 ---
    gemm_small_kernel<<<gg64, 256, SG_SMEM>>>(h0, W0th, W0tl, hW);
    attn_fused_kernel<false><<<BT / RPB, 256, ATTN_SMEM>>>(
        h0, hW, asrc0, adst0, g0, b0, nullptr, nullptr, h1);

    // --- GAT block 1 (final LN fused, writes d_out) ---
    gemm_small_kernel<<<gg64, 256, SG_SMEM>>>(h1, W1th, W1tl, hW);
    attn_fused_kernel<true><<<BT / RPB, 256, ATTN_SMEM>>>(
        h1, hW, asrc1, adst1, g1, b1, gF, bF, out);
}

// round 12
// speedup vs baseline: 1.0006x; 1.0006x over previous
#include <cuda_runtime.h>
#include <cuda_bf16.h>
#include <math.h>
#include <stdint.h>

// Problem constants
#define BB      2
#define TT      2048
#define DD      2048
#define HH      256
#define BT      (BB*TT)        // 4096 rows
#define NHEADS  4
#define HD      64
#define WINR    15
#define EPSV    1e-5f

// ---------------- scratch (device globals; allocation-free) ----------------
__device__ float g_h0[BT*HH];
__device__ float g_h1[BT*HH];
__device__ float g_hW[BT*HH];
__device__ __nv_bfloat16 g_Wpt_hi[HH*DD];
__device__ __nv_bfloat16 g_Wpt_lo[HH*DD];
__device__ __nv_bfloat16 g_W0t_hi[HH*HH];
__device__ __nv_bfloat16 g_W0t_lo[HH*HH];
__device__ __nv_bfloat16 g_W1t_hi[HH*HH];
__device__ __nv_bfloat16 g_W1t_lo[HH*HH];

// ---------------- helpers ----------------
__device__ __forceinline__ uint32_t smem_u32(const void* p) {
    uint32_t a;
    asm("{ .reg .u64 t; cvta.to.shared.u64 t, %1; cvt.u32.u64 %0, t; }"
        : "=r"(a) : "l"(p));
    return a;
}
__device__ __forceinline__ uint32_t swz(uint32_t off) {   // SW128 XOR swizzle
    return off ^ ((off >> 3) & 0x70);
}
__device__ __forceinline__ void ldm_x4(uint32_t& r0, uint32_t& r1, uint32_t& r2,
                                       uint32_t& r3, uint32_t addr) {
    asm volatile("ldmatrix.sync.aligned.m8n8.x4.shared.b16 {%0,%1,%2,%3}, [%4];"
                 : "=r"(r0), "=r"(r1), "=r"(r2), "=r"(r3) : "r"(addr));
}
__device__ __forceinline__ void mma_bf16(float* d, const uint32_t* a, const uint32_t* b) {
    asm volatile(
        "mma.sync.aligned.m16n8k16.row.col.f32.bf16.bf16.f32 "
        "{%0,%1,%2,%3}, {%4,%5,%6,%7}, {%8,%9}, {%0,%1,%2,%3};"
        : "+f"(d[0]), "+f"(d[1]), "+f"(d[2]), "+f"(d[3])
        : "r"(a[0]), "r"(a[1]), "r"(a[2]), "r"(a[3]), "r"(b[0]), "r"(b[1]));
}
__device__ __forceinline__ uint32_t pack_bf16(float x, float y) {
    __nv_bfloat162 p(__float2bfloat16(x), __float2bfloat16(y));
    return *reinterpret_cast<uint32_t*>(&p);
}
__device__ __forceinline__ void cp_async16(uint32_t dst, const void* src) {
    asm volatile("cp.async.cg.shared.global [%0], [%1], 16;"
                 :: "r"(dst), "l"(src) : "memory");
}
__device__ __forceinline__ void cp_commit() {
    asm volatile("cp.async.commit_group;" ::: "memory");
}
__device__ __forceinline__ void cp_wait0() {
    asm volatile("cp.async.wait_group 0;" ::: "memory");
}

// ---------------------------------------------------------------------------
// Weight prep: smem-tiled transpose + bf16 split (32x32 tiles).
// ---------------------------------------------------------------------------
__global__ __launch_bounds__(256) void wprep_tiled_kernel(
    const float* __restrict__ Wp, __nv_bfloat16* __restrict__ Wph, __nv_bfloat16* __restrict__ Wpl,
    const float* __restrict__ W0, __nv_bfloat16* __restrict__ W0h, __nv_bfloat16* __restrict__ W0l,
    const float* __restrict__ W1, __nv_bfloat16* __restrict__ W1h, __nv_bfloat16* __restrict__ W1l)
{
    int blk = blockIdx.x;
    const float* W; __nv_bfloat16 *Wh, *Wl; int K, N;
    if (blk < 512)      { W = Wp; Wh = Wph; Wl = Wpl; K = DD; N = HH; }
    else if (blk < 576) { W = W0; Wh = W0h; Wl = W0l; K = HH; N = HH; blk -= 512; }
    else                { W = W1; Wh = W1h; Wl = W1l; K = HH; N = HH; blk -= 576; }
    const int tpr = N / 32;
    const int tk = blk / tpr, tn = blk - tk * tpr;

    __shared__ float ts[32][33];
    const int r = threadIdx.x >> 5, c = threadIdx.x & 31;
#pragma unroll
    for (int i = 0; i < 4; i++)
        ts[r + i * 8][c] = W[(size_t)(tk * 32 + r + i * 8) * N + tn * 32 + c];
    __syncthreads();
#pragma unroll
    for (int i = 0; i < 4; i++) {
        int nn = tn * 32 + r + i * 8;
        float v = ts[c][r + i * 8];
        __nv_bfloat16 hi = __float2bfloat16(v);
        __nv_bfloat16 lo = __float2bfloat16(v - __bfloat162float(hi));
        size_t o = (size_t)nn * K + tk * 32 + c;
        Wh[o] = hi;
        Wl[o] = lo;
    }
}

// ---------------------------------------------------------------------------
// Projection GEMM 128x64, BK=32, double-buffered, split-K via gridDim.z.
// ---------------------------------------------------------------------------
#define GBM 128
#define GBN 64
#define GBK 32

template<int NSPLIT>
__global__ __launch_bounds__(256) void gemm_mma_kernel(
    const float* __restrict__ A, const __nv_bfloat16* __restrict__ Bhi,
    const __nv_bfloat16* __restrict__ Blo, const float* __restrict__ bias,
    float* __restrict__ C0, float* __restrict__ C1, int K)
{
    __shared__ __align__(1024) uint8_t sA[2][GBM * 128];
    __shared__ __align__(1024) uint8_t sB[2][GBN * 128];
    const uint32_t sAb0 = smem_u32(sA[0]), sAb1 = smem_u32(sA[1]);
    const uint32_t sBb0 = smem_u32(sB[0]), sBb1 = smem_u32(sB[1]);

    const int tid = threadIdx.x, wid = tid >> 5, lane = tid & 31;
    const int row0 = blockIdx.y * GBM;
    const int n0   = blockIdx.x * GBN;
    const int ksec  = K / NSPLIT;
    const int kbase = (NSPLIT > 1) ? blockIdx.z * ksec : 0;
    float* __restrict__ C = (NSPLIT > 1 && blockIdx.z == 1) ? C1 : C0;
    const int warpM = (wid >> 1) * 32;
    const int warpN = (wid & 1) * 32;

    float d[2][4][4];
#pragma unroll
    for (int mt = 0; mt < 2; mt++)
#pragma unroll
        for (int nt = 0; nt < 4; nt++)
#pragma unroll
            for (int i = 0; i < 4; i++) d[mt][nt][i] = 0.f;

    const int bn = tid >> 2, bq = tid & 3;
    const int NIT = ksec / GBK;
    float4 aR[4];

    auto ldgA = [&](int it) {
        const int k0 = kbase + it * GBK;
#pragma unroll
        for (int i = 0; i < 4; i++) {
            int slot = tid + i * 256;
            int r = slot >> 3, c = slot & 7;
            aR[i] = *reinterpret_cast<const float4*>(
                &A[(size_t)(row0 + r) * K + k0 + c * 4]);
        }
    };
    auto cpB = [&](int it, uint32_t sBb) {
        const int k0 = kbase + it * GBK;
        cp_async16(sBb + swz((uint32_t)(bn * 128 + bq * 16)),
                   &Bhi[(size_t)(n0 + bn) * K + k0 + bq * 8]);
        cp_async16(sBb + swz((uint32_t)(bn * 128 + 64 + bq * 16)),
                   &Blo[(size_t)(n0 + bn) * K + k0 + bq * 8]);
        cp_commit();
    };
    auto stsA = [&](uint8_t* dst) {
#pragma unroll
        for (int i = 0; i < 4; i++) {
            int slot = tid + i * 256;
            int r = slot >> 3, c = slot & 7;
            float4 v = aR[i];
            uint32_t h0 = pack_bf16(v.x, v.y), h1 = pack_bf16(v.z, v.w);
            float rx = v.x - __bfloat162float(__float2bfloat16(v.x));
            float ry = v.y - __bfloat162float(__float2bfloat16(v.y));
            float rz = v.z - __bfloat162float(__float2bfloat16(v.z));
            float rw = v.w - __bfloat162float(__float2bfloat16(v.w));
            uint32_t l0 = pack_bf16(rx, ry), l1 = pack_bf16(rz, rw);
            *reinterpret_cast<uint2*>(dst + swz((uint32_t)(r * 128 + c * 8)))
                = make_uint2(h0, h1);
            *reinterpret_cast<uint2*>(dst + swz((uint32_t)(r * 128 + 64 + c * 8)))
                = make_uint2(l0, l1);
        }
    };

    ldgA(0);
    cpB(0, sBb0);
    stsA(sA[0]);
    if (NIT > 1) ldgA(1);
    cp_wait0();
    __syncthreads();

    for (int it = 0; it < NIT; ++it) {
        const int s = it & 1;
        const uint32_t sAb = s ? sAb1 : sAb0;
        const uint32_t sBb = s ? sBb1 : sBb0;

        if (it + 1 < NIT) {
            cpB(it + 1, s ? sBb0 : sBb1);
            stsA(s ? sA[0] : sA[1]);
            if (it + 2 < NIT) ldgA(it + 2);
        }

#pragma unroll
        for (int kk = 0; kk < 2; kk++) {
            uint32_t ahi[2][4], alo[2][4], bhi[4][2], blo[4][2];
#pragma unroll
            for (int mt = 0; mt < 2; mt++) {
                int mrow = warpM + mt * 16 + (lane & 15);
                uint32_t kbyte = (uint32_t)((kk * 16 + ((lane >> 4) << 3)) * 2);
                ldm_x4(ahi[mt][0], ahi[mt][1], ahi[mt][2], ahi[mt][3],
                       sAb + swz((uint32_t)(mrow * 128) + kbyte));
                ldm_x4(alo[mt][0], alo[mt][1], alo[mt][2], alo[mt][3],
                       sAb + swz((uint32_t)(mrow * 128) + 64u + kbyte));
            }
#pragma unroll
            for (int p = 0; p < 2; p++) {
                int sel = lane >> 3, l8 = lane & 7;
                int nrow = warpN + p * 16 + ((sel & 2) ? 8 : 0) + l8;
                uint32_t kbyte = (uint32_t)((kk * 16 + (sel & 1) * 8) * 2);
                uint32_t q0, q1, q2, q3;
                ldm_x4(q0, q1, q2, q3, sBb + swz((uint32_t)(nrow * 128) + kbyte));
                bhi[p * 2 + 0][0] = q0; bhi[p * 2 + 0][1] = q1;
                bhi[p * 2 + 1][0] = q2; bhi[p * 2 + 1][1] = q3;
                ldm_x4(q0, q1, q2, q3, sBb + swz((uint32_t)(nrow * 128) + 64u + kbyte));
                blo[p * 2 + 0][0] = q0; blo[p * 2 + 0][1] = q1;
                blo[p * 2 + 1][0] = q2; blo[p * 2 + 1][1] = q3;
            }
#pragma unroll
            for (int mt = 0; mt < 2; mt++)
#pragma unroll
                for (int nt = 0; nt < 4; nt++) {
                    mma_bf16(d[mt][nt], ahi[mt], bhi[nt]);
                    mma_bf16(d[mt][nt], alo[mt], bhi[nt]);
                    mma_bf16(d[mt][nt], ahi[mt], blo[nt]);
                }
        }

        if (it + 1 < NIT) cp_wait0();
        __syncthreads();
    }

    const int rq = lane >> 2, cq = (lane & 3) * 2;
#pragma unroll
    for (int mt = 0; mt < 2; mt++)
#pragma unroll
        for (int nt = 0; nt < 4; nt++) {
            int row = row0 + warpM + mt * 16 + rq;
            int col = n0 + warpN + nt * 8 + cq;
            float b0 = 0.f, b1 = 0.f;
            if (NSPLIT == 1 && bias) { b0 = bias[col]; b1 = bias[col + 1]; }
            *reinterpret_cast<float2*>(&C[(size_t)row * HH + col]) =
                make_float2(d[mt][nt][0] + b0, d[mt][nt][1] + b1);
            *reinterpret_cast<float2*>(&C[(size_t)(row + 8) * HH + col]) =
                make_float2(d[mt][nt][2] + b0, d[mt][nt][3] + b1);
        }
}

// ---------------------------------------------------------------------------
// Small-GEMM (R10-verified): CTA tile 64x64, BK=32, double-buffered,
// 2 CTAs/SM (grid 256), 8 warps (4Mx2N, warp tile 16x32).
// ---------------------------------------------------------------------------
__global__ __launch_bounds__(256) void gemm_mma64_kernel(
    const float* __restrict__ A, const __nv_bfloat16* __restrict__ Bhi,
    const __nv_bfloat16* __restrict__ Blo,
    float* __restrict__ C, int K)
{
    __shared__ __align__(1024) uint8_t sA[2][64 * 128];   // 2 x 8 KB
    __shared__ __align__(1024) uint8_t sB[2][64 * 128];   // 2 x 8 KB
    const uint32_t sAb0 = smem_u32(sA[0]), sAb1 = smem_u32(sA[1]);
    const uint32_t sBb0 = smem_u32(sB[0]), sBb1 = smem_u32(sB[1]);

    const int tid = threadIdx.x, wid = tid >> 5, lane = tid & 31;
    const int row0 = blockIdx.y * 64;
    const int n0   = blockIdx.x * 64;
    const int warpM = (wid >> 1) * 16;
    const int warpN = (wid & 1) * 32;

    float d[4][4];
#pragma unroll
    for (int nt = 0; nt < 4; nt++)
#pragma unroll
        for (int i = 0; i < 4; i++) d[nt][i] = 0.f;

    const int bn = tid >> 2, bq = tid & 3;
    const int NIT = K / GBK;
    float4 aR[2];

    auto ldgA = [&](int it) {
        const int k0 = it * GBK;
#pragma unroll
        for (int i = 0; i < 2; i++) {
            int slot = tid + i * 256;
            int r = slot >> 3, c = slot & 7;
            aR[i] = *reinterpret_cast<const float4*>(
                &A[(size_t)(row0 + r) * K + k0 + c * 4]);
        }
    };
    auto cpB = [&](int it, uint32_t sBb) {
        const int k0 = it * GBK;
        cp_async16(sBb + swz((uint32_t)(bn * 128 + bq * 16)),
                   &Bhi[(size_t)(n0 + bn) * K + k0 + bq * 8]);
        cp_async16(sBb + swz((uint32_t)(bn * 128 + 64 + bq * 16)),
                   &Blo[(size_t)(n0 + bn) * K + k0 + bq * 8]);
        cp_commit();
    };
    auto stsA = [&](uint8_t* dst) {
#pragma unroll
        for (int i = 0; i < 2; i++) {
            int slot = tid + i * 256;
            int r = slot >> 3, c = slot & 7;
            float4 v = aR[i];
            uint32_t h0 = pack_bf16(v.x, v.y), h1 = pack_bf16(v.z, v.w);
            float rx = v.x - __bfloat162float(__float2bfloat16(v.x));
            float ry = v.y - __bfloat162float(__float2bfloat16(v.y));
            float rz = v.z - __bfloat162float(__float2bfloat16(v.z));
            float rw = v.w - __bfloat162float(__float2bfloat16(v.w));
            uint32_t l0 = pack_bf16(rx, ry), l1 = pack_bf16(rz, rw);
            *reinterpret_cast<uint2*>(dst + swz((uint32_t)(r * 128 + c * 8)))
                = make_uint2(h0, h1);
            *reinterpret_cast<uint2*>(dst + swz((uint32_t)(r * 128 + 64 + c * 8)))
                = make_uint2(l0, l1);
        }
    };

    ldgA(0);
    cpB(0, sBb0);
    stsA(sA[0]);
    if (NIT > 1) ldgA(1);
    cp_wait0();
    __syncthreads();

    for (int it = 0; it < NIT; ++it) {
        const int s = it & 1;
        const uint32_t sAb = s ? sAb1 : sAb0;
        const uint32_t sBb = s ? sBb1 : sBb0;

        if (it + 1 < NIT) {
            cpB(it + 1, s ? sBb0 : sBb1);
            stsA(s ? sA[0] : sA[1]);
            if (it + 2 < NIT) ldgA(it + 2);
        }

#pragma unroll
        for (int kk = 0; kk < 2; kk++) {
            uint32_t ahi[4], alo[4], bhi[4][2], blo[4][2];
            {
                int mrow = warpM + (lane & 15);
                uint32_t kbyte = (uint32_t)((kk * 16 + ((lane >> 4) << 3)) * 2);
                ldm_x4(ahi[0], ahi[1], ahi[2], ahi[3],
                       sAb + swz((uint32_t)(mrow * 128) + kbyte));
                ldm_x4(alo[0], alo[1], alo[2], alo[3],
                       sAb + swz((uint32_t)(mrow * 128) + 64u + kbyte));
            }
#pragma unroll
            for (int p = 0; p < 2; p++) {
                int sel = lane >> 3, l8 = lane & 7;
                int nrow = warpN + p * 16 + ((sel & 2) ? 8 : 0) + l8;
                uint32_t kbyte = (uint32_t)((kk * 16 + (sel & 1) * 8) * 2);
                uint32_t q0, q1, q2, q3;
                ldm_x4(q0, q1, q2, q3, sBb + swz((uint32_t)(nrow * 128) + kbyte));
                bhi[p * 2 + 0][0] = q0; bhi[p * 2 + 0][1] = q1;
                bhi[p * 2 + 1][0] = q2; bhi[p * 2 + 1][1] = q3;
                ldm_x4(q0, q1, q2, q3, sBb + swz((uint32_t)(nrow * 128) + 64u + kbyte));
                blo[p * 2 + 0][0] = q0; blo[p * 2 + 0][1] = q1;
                blo[p * 2 + 1][0] = q2; blo[p * 2 + 1][1] = q3;
            }
#pragma unroll
            for (int nt = 0; nt < 4; nt++) {
                mma_bf16(d[nt], ahi, bhi[nt]);
                mma_bf16(d[nt], alo, bhi[nt]);
                mma_bf16(d[nt], ahi, blo[nt]);
            }
        }

        if (it + 1 < NIT) cp_wait0();
        __syncthreads();
    }

    const int rq = lane >> 2, cq = (lane & 3) * 2;
#pragma unroll
    for (int nt = 0; nt < 4; nt++) {
        int row = row0 + warpM + rq;
        int col = n0 + warpN + nt * 8 + cq;
        *reinterpret_cast<float2*>(&C[(size_t)row * HH + col]) =
            make_float2(d[nt][0], d[nt][1]);
        *reinterpret_cast<float2*>(&C[(size_t)(row + 8) * HH + col]) =
            make_float2(d[nt][2], d[nt][3]);
    }
}

// ---------------------------------------------------------------------------
// Split-K reduction: C = P0 + P1 + bias
// ---------------------------------------------------------------------------
__global__ __launch_bounds__(256) void addbias_kernel(
    const float* __restrict__ P0, const float* __restrict__ P1,
    const float* __restrict__ bias, float* __restrict__ C)
{
    int i = blockIdx.x * 256 + threadIdx.x;
    int col = (i * 4) & (HH - 1);
    float4 a = *reinterpret_cast<const float4*>(&P0[(size_t)i * 4]);
    float4 b = *reinterpret_cast<const float4*>(&P1[(size_t)i * 4]);
    float4 bv = *reinterpret_cast<const float4*>(&bias[col]);
    *reinterpret_cast<float4*>(&C[(size_t)i * 4]) =
        make_float4(a.x + b.x + bv.x, a.y + b.y + bv.y,
                    a.z + b.z + bv.z, a.w + b.w + bv.w);
}

// ---------------------------------------------------------------------------
// Fused attention: RPB=16, zero-padded tile, JOINT 2-row register aggregation,
// + residual + LN (+ final LN). 2 CTAs/SM.
// ---------------------------------------------------------------------------
#define RPB   16
#define NTROW (RPB + 2*WINR)              // 46
#define NJ    (2*WINR + 1)                // 31
#define WST   33
#define AT_TILE 0
#define AT_ES   47104
#define AT_ED   47872
#define AT_SA   48640
#define AT_SD   49664
#define AT_W    50688
#define ATTN_SMEM 59136

template<bool FINAL_LN>
__global__ __launch_bounds__(256, 2) void attn_fused_kernel(
    const float* __restrict__ h,  const float* __restrict__ hW,
    const float* __restrict__ asrc, const float* __restrict__ adst,
    const float* __restrict__ g,  const float* __restrict__ b,
    const float* __restrict__ gF, const float* __restrict__ bF,
    float* __restrict__ out)
{
    extern __shared__ char sm[];
    float* tile = (float*)(sm + AT_TILE);
    float* es_s = (float*)(sm + AT_ES);
    float* ed_s = (float*)(sm + AT_ED);
    float* sa   = (float*)(sm + AT_SA);
    float* sd   = (float*)(sm + AT_SD);
    float* wsm  = (float*)(sm + AT_W);

    const int tid = threadIdx.x, wid = tid >> 5, lane = tid & 31;
    const int bpb = TT / RPB;
    const int batch = blockIdx.x / bpb;
    const int t0 = (blockIdx.x - batch * bpb) * RPB;
    const int gbase = batch * TT;

    for (int idx = tid; idx < NTROW * 64; idx += 256) {
        int r = idx >> 6, c4 = idx & 63;
        int tg = t0 - WINR + r;
        float4 v = make_float4(0.f, 0.f, 0.f, 0.f);
        if (tg >= 0 && tg < TT)
            v = *reinterpret_cast<const float4*>(
                &hW[(size_t)(gbase + tg) * HH + c4 * 4]);
        *reinterpret_cast<float4*>(&tile[r * 256 + c4 * 4]) = v;
    }
    sa[tid] = asrc[tid];
    sd[tid] = adst[tid];
    __syncthreads();

    {
        const int head = lane >> 3, dk = lane & 7;
        const int base4 = head * 16 + dk * 2;
        float4 s0 = *reinterpret_cast<float4*>(&sa[base4 * 4]);
        float4 s1 = *reinterpret_cast<float4*>(&sa[base4 * 4 + 4]);
        float4 dd0 = *reinterpret_cast<float4*>(&sd[base4 * 4]);
        float4 dd1 = *reinterpret_cast<float4*>(&sd[base4 * 4 + 4]);
        for (int r = wid; r < NTROW; r += 8) {
            float4 v0 = *reinterpret_cast<float4*>(&tile[r * 256 + base4 * 4]);
            float4 v1 = *reinterpret_cast<float4*>(&tile[r * 256 + base4 * 4 + 4]);
            float ps = v0.x*s0.x + v0.y*s0.y + v0.z*s0.z + v0.w*s0.w
                     + v1.x*s1.x + v1.y*s1.y + v1.z*s1.z + v1.w*s1.w;
            float pd = v0.x*dd0.x + v0.y*dd0.y + v0.z*dd0.z + v0.w*dd0.w
                     + v1.x*dd1.x + v1.y*dd1.y + v1.z*dd1.z + v1.w*dd1.w;
#pragma unroll
            for (int o = 4; o > 0; o >>= 1) {
                ps += __shfl_xor_sync(0xffffffffu, ps, o);
                pd += __shfl_xor_sync(0xffffffffu, pd, o);
            }
            if (dk == 0) { es_s[r * 4 + head] = ps; ed_s[r * 4 + head] = pd; }
        }
    }
    __syncthreads();

#pragma unroll
    for (int q = 0; q < 8; q++) {
        int p = wid + 8 * q;
        int r = p >> 2, head = p & 3;
        int t = t0 + r;
        int tn = t - WINR + lane;
        bool valid = (lane < NJ) && (tn >= 0) && (tn < TT);
        float e = -1e30f;
        if (valid) {
            float v = es_s[(r + WINR) * 4 + head] + ed_s[(r + lane) * 4 + head];
            e = (v > 0.f) ? v : 0.2f * v;
        }
        float m = e;
#pragma unroll
        for (int o = 16; o > 0; o >>= 1) m = fmaxf(m, __shfl_xor_sync(0xffffffffu, m, o));
        float xv = valid ? __expf(e - m) : 0.f;
        float s = xv;
#pragma unroll
        for (int o = 16; o > 0; o >>= 1) s += __shfl_xor_sync(0xffffffffu, s, o);
        wsm[p * WST + lane] = xv / s;    // lane 31 stores exactly 0
    }
    __syncthreads();

    // --- joint 2-row aggregation: rows r0=2*wid, r0+1 share tile rows ---
    const int c0 = lane * 8;
    const int head = lane >> 3;
    const int r0 = wid * 2;
    const float* w0 = &wsm[(r0 * 4 + head) * WST];
    const float* w1 = &wsm[((r0 + 1) * 4 + head) * WST];
    float a0[8], a1[8];
#pragma unroll
    for (int k = 0; k < 8; k++) { a0[k] = 0.f; a1[k] = 0.f; }
#pragma unroll
    for (int u = 0; u < 32; u++) {
        const float* trow = &tile[(r0 + u) * 256 + c0];
        float4 t0v = *reinterpret_cast<const float4*>(trow);
        float4 t1v = *reinterpret_cast<const float4*>(trow + 4);
        float wa = w0[u];                         // w0[31] == 0
        float wb = (u == 0) ? 0.f : w1[u - 1];
        a0[0] = fmaf(wa, t0v.x, a0[0]); a0[1] = fmaf(wa, t0v.y, a0[1]);
        a0[2] = fmaf(wa, t0v.z, a0[2]); a0[3] = fmaf(wa, t0v.w, a0[3]);
        a0[4] = fmaf(wa, t1v.x, a0[4]); a0[5] = fmaf(wa, t1v.y, a0[5]);
        a0[6] = fmaf(wa, t1v.z, a0[6]); a0[7] = fmaf(wa, t1v.w, a0[7]);
        a1[0] = fmaf(wb, t0v.x, a1[0]); a1[1] = fmaf(wb, t0v.y, a1[1]);
        a1[2] = fmaf(wb, t0v.z, a1[2]); a1[3] = fmaf(wb, t0v.w, a1[3]);
        a1[4] = fmaf(wb, t1v.x, a1[4]); a1[5] = fmaf(wb, t1v.y, a1[5]);
        a1[6] = fmaf(wb, t1v.z, a1[6]); a1[7] = fmaf(wb, t1v.w, a1[7]);
    }

    // --- per-row residual + LN (+ final LN) + store ---
#pragma unroll
    for (int rr = 0; rr < 2; rr++) {
        float* a = rr ? a1 : a0;
        const int r = r0 + rr;
        const size_t grow = (size_t)(gbase + t0 + r) * HH;
        float4 h0v = *reinterpret_cast<const float4*>(&h[grow + c0]);
        float4 h1v = *reinterpret_cast<const float4*>(&h[grow + c0 + 4]);
        a[0] += h0v.x; a[1] += h0v.y; a[2] += h0v.z; a[3] += h0v.w;
        a[4] += h1v.x; a[5] += h1v.y; a[6] += h1v.z; a[7] += h1v.w;
        float s1 = 0.f, s2 = 0.f;
#pragma unroll
        for (int k = 0; k < 8; k++) { s1 += a[k]; s2 += a[k] * a[k]; }
#pragma unroll
        for (int o = 16; o > 0; o >>= 1) {
            s1 += __shfl_xor_sync(0xffffffffu, s1, o);
            s2 += __shfl_xor_sync(0xffffffffu, s2, o);
        }
        float mu  = s1 * (1.f / 256.f);
        float var = s2 * (1.f / 256.f) - mu * mu;
        float inv = rsqrtf(var + EPSV);
        float4 g0v = *reinterpret_cast<const float4*>(&g[c0]);
        float4 g1v = *reinterpret_cast<const float4*>(&g[c0 + 4]);
        float4 b0v = *reinterpret_cast<const float4*>(&b[c0]);
        float4 b1v = *reinterpret_cast<const float4*>(&b[c0 + 4]);
        float z[8];
        z[0] = (a[0]-mu)*inv*g0v.x + b0v.x; z[1] = (a[1]-mu)*inv*g0v.y + b0v.y;
        z[2] = (a[2]-mu)*inv*g0v.z + b0v.z; z[3] = (a[3]-mu)*inv*g0v.w + b0v.w;
        z[4] = (a[4]-mu)*inv*g1v.x + b1v.x; z[5] = (a[5]-mu)*inv*g1v.y + b1v.y;
        z[6] = (a[6]-mu)*inv*g1v.z + b1v.z; z[7] = (a[7]-mu)*inv*g1v.w + b1v.w;
        if (FINAL_LN) {
            float z1 = 0.f, z2 = 0.f;
#pragma unroll
            for (int k = 0; k < 8; k++) { z1 += z[k]; z2 += z[k] * z[k]; }
#pragma unroll
            for (int o = 16; o > 0; o >>= 1) {
                z1 += __shfl_xor_sync(0xffffffffu, z1, o);
                z2 += __shfl_xor_sync(0xffffffffu, z2, o);
            }
            float mu2  = z1 * (1.f / 256.f);
            float var2 = z2 * (1.f / 256.f) - mu2 * mu2;
            float inv2 = rsqrtf(var2 + EPSV);
            float4 gf0 = *reinterpret_cast<const float4*>(&gF[c0]);
            float4 gf1 = *reinterpret_cast<const float4*>(&gF[c0 + 4]);
            float4 bf0 = *reinterpret_cast<const float4*>(&bF[c0]);
            float4 bf1 = *reinterpret_cast<const float4*>(&bF[c0 + 4]);
            z[0] = (z[0]-mu2)*inv2*gf0.x + bf0.x; z[1] = (z[1]-mu2)*inv2*gf0.y + bf0.y;
            z[2] = (z[2]-mu2)*inv2*gf0.z + bf0.z; z[3] = (z[3]-mu2)*inv2*gf0.w + bf0.w;
            z[4] = (z[4]-mu2)*inv2*gf1.x + bf1.x; z[5] = (z[5]-mu2)*inv2*gf1.y + bf1.y;
            z[6] = (z[6]-mu2)*inv2*gf1.z + bf1.z; z[7] = (z[7]-mu2)*inv2*gf1.w + bf1.w;
        }
        *reinterpret_cast<float4*>(&out[grow + c0]) =
            make_float4(z[0], z[1], z[2], z[3]);
        *reinterpret_cast<float4*>(&out[grow + c0 + 4]) =
            make_float4(z[4], z[5], z[6], z[7]);
    }
}

// ---------------------------------------------------------------------------
extern "C" void kernel_launch(void* const* d_in, const int* in_sizes, int n_in,
                              void* d_out, int out_size)
{
    const float* x     = (const float*)d_in[0];
    // d_in[1] = adj_mask (banded window reconstructed analytically; unused)
    const float* Wp    = (const float*)d_in[2];
    const float* bp    = (const float*)d_in[3];
    const float* W0    = (const float*)d_in[4];
    const float* asrc0 = (const float*)d_in[5];
    const float* adst0 = (const float*)d_in[6];
    const float* g0    = (const float*)d_in[7];
    const float* b0    = (const float*)d_in[8];
    const float* W1    = (const float*)d_in[9];
    const float* asrc1 = (const float*)d_in[10];
    const float* adst1 = (const float*)d_in[11];
    const float* g1    = (const float*)d_in[12];
    const float* b1    = (const float*)d_in[13];
    const float* gF    = (const float*)d_in[14];
    const float* bF    = (const float*)d_in[15];
    float* out = (float*)d_out;

    float *h0, *h1, *hW;
    __nv_bfloat16 *Wpth, *Wptl, *W0th, *W0tl, *W1th, *W1tl;
    cudaGetSymbolAddress((void**)&h0, g_h0);
    cudaGetSymbolAddress((void**)&h1, g_h1);
    cudaGetSymbolAddress((void**)&hW, g_hW);
    cudaGetSymbolAddress((void**)&Wpth, g_Wpt_hi);
    cudaGetSymbolAddress((void**)&Wptl, g_Wpt_lo);
    cudaGetSymbolAddress((void**)&W0th, g_W0t_hi);
    cudaGetSymbolAddress((void**)&W0tl, g_W0t_lo);
    cudaGetSymbolAddress((void**)&W1th, g_W1t_hi);
    cudaGetSymbolAddress((void**)&W1tl, g_W1t_lo);

    cudaFuncSetAttribute(attn_fused_kernel<false>,
        cudaFuncAttributeMaxDynamicSharedMemorySize, ATTN_SMEM);
    cudaFuncSetAttribute(attn_fused_kernel<true>,
        cudaFuncAttributeMaxDynamicSharedMemorySize, ATTN_SMEM);

    // Weight prep: tiled transpose, 640 blocks
    wprep_tiled_kernel<<<640, 256>>>(
        Wp, Wpth, Wptl, W0, W0th, W0tl, W1, W1th, W1tl);

    // ---- projection: split-K=2 partials + reduce ----
    dim3 gProj(HH / GBN, BT / GBM, 2);      // (4, 32, 2) = 256 CTAs
    gemm_mma_kernel<2><<<gProj, 256>>>(x, Wpth, Wptl, nullptr, h1, hW, DD);
    addbias_kernel<<<(BT * HH / 4) / 256, 256>>>(h1, hW, bp, h0);

    dim3 gg64(HH / 64, BT / 64);            // (4, 64) = 256 CTAs

    // --- GAT block 0 ---
    gemm_mma64_kernel<<<gg64, 256>>>(h0, W0th, W0tl, hW, HH);
    attn_fused_kernel<false><<<BT / RPB, 256, ATTN_SMEM>>>(
        h0, hW, asrc0, adst0, g0, b0, nullptr, nullptr, h1);

    // --- GAT block 1 (final LN fused, writes d_out) ---
    gemm_mma64_kernel<<<gg64, 256>>>(h1, W1th, W1tl, hW, HH);
    attn_fused_kernel<true><<<BT / RPB, 256, ATTN_SMEM>>>(
        h1, hW, asrc1, adst1, g1, b1, gF, bF, out);
}

// round 13
// speedup vs baseline: 1.0195x; 1.0189x over previous
#include <cuda_runtime.h>
#include <cuda_bf16.h>
#include <math.h>
#include <stdint.h>

// Problem constants
#define BB      2
#define TT      2048
#define DD      2048
#define HH      256
#define BT      (BB*TT)        // 4096 rows
#define NHEADS  4
#define HD      64
#define WINR    15
#define EPSV    1e-5f

// ---------------- scratch (device globals; allocation-free) ----------------
__device__ float g_h0[BT*HH];
__device__ float g_h1[BT*HH];
__device__ float g_hW[BT*HH];
__device__ __nv_bfloat16 g_Wpt_hi[HH*DD];
__device__ __nv_bfloat16 g_Wpt_lo[HH*DD];
__device__ __nv_bfloat16 g_W0t_hi[HH*HH];
__device__ __nv_bfloat16 g_W0t_lo[HH*HH];
__device__ __nv_bfloat16 g_W1t_hi[HH*HH];
__device__ __nv_bfloat16 g_W1t_lo[HH*HH];

// ---------------- helpers ----------------
__device__ __forceinline__ uint32_t smem_u32(const void* p) {
    uint32_t a;
    asm("{ .reg .u64 t; cvta.to.shared.u64 t, %1; cvt.u32.u64 %0, t; }"
        : "=r"(a) : "l"(p));
    return a;
}
__device__ __forceinline__ uint32_t swz(uint32_t off) {   // SW128 XOR swizzle
    return off ^ ((off >> 3) & 0x70);
}
__device__ __forceinline__ void ldm_x4(uint32_t& r0, uint32_t& r1, uint32_t& r2,
                                       uint32_t& r3, uint32_t addr) {
    asm volatile("ldmatrix.sync.aligned.m8n8.x4.shared.b16 {%0,%1,%2,%3}, [%4];"
                 : "=r"(r0), "=r"(r1), "=r"(r2), "=r"(r3) : "r"(addr));
}
__device__ __forceinline__ void mma_bf16(float* d, const uint32_t* a, const uint32_t* b) {
    asm volatile(
        "mma.sync.aligned.m16n8k16.row.col.f32.bf16.bf16.f32 "
        "{%0,%1,%2,%3}, {%4,%5,%6,%7}, {%8,%9}, {%0,%1,%2,%3};"
        : "+f"(d[0]), "+f"(d[1]), "+f"(d[2]), "+f"(d[3])
        : "r"(a[0]), "r"(a[1]), "r"(a[2]), "r"(a[3]), "r"(b[0]), "r"(b[1]));
}
__device__ __forceinline__ uint32_t pack_bf16(float x, float y) {
    __nv_bfloat162 p(__float2bfloat16(x), __float2bfloat16(y));
    return *reinterpret_cast<uint32_t*>(&p);
}
__device__ __forceinline__ void cp_async16(uint32_t dst, const void* src) {
    asm volatile("cp.async.cg.shared.global [%0], [%1], 16;"
                 :: "r"(dst), "l"(src) : "memory");
}
__device__ __forceinline__ void cp_commit() {
    asm volatile("cp.async.commit_group;" ::: "memory");
}
__device__ __forceinline__ void cp_wait0() {
    asm volatile("cp.async.wait_group 0;" ::: "memory");
}

// ---------------------------------------------------------------------------
// Weight prep: smem-tiled transpose + bf16 split (32x32 tiles).
// ---------------------------------------------------------------------------
__global__ __launch_bounds__(256) void wprep_tiled_kernel(
    const float* __restrict__ Wp, __nv_bfloat16* __restrict__ Wph, __nv_bfloat16* __restrict__ Wpl,
    const float* __restrict__ W0, __nv_bfloat16* __restrict__ W0h, __nv_bfloat16* __restrict__ W0l,
    const float* __restrict__ W1, __nv_bfloat16* __restrict__ W1h, __nv_bfloat16* __restrict__ W1l)
{
    int blk = blockIdx.x;
    const float* W; __nv_bfloat16 *Wh, *Wl; int K, N;
    if (blk < 512)      { W = Wp; Wh = Wph; Wl = Wpl; K = DD; N = HH; }
    else if (blk < 576) { W = W0; Wh = W0h; Wl = W0l; K = HH; N = HH; blk -= 512; }
    else                { W = W1; Wh = W1h; Wl = W1l; K = HH; N = HH; blk -= 576; }
    const int tpr = N / 32;
    const int tk = blk / tpr, tn = blk - tk * tpr;

    __shared__ float ts[32][33];
    const int r = threadIdx.x >> 5, c = threadIdx.x & 31;
#pragma unroll
    for (int i = 0; i < 4; i++)
        ts[r + i * 8][c] = W[(size_t)(tk * 32 + r + i * 8) * N + tn * 32 + c];
    __syncthreads();
#pragma unroll
    for (int i = 0; i < 4; i++) {
        int nn = tn * 32 + r + i * 8;
        float v = ts[c][r + i * 8];
        __nv_bfloat16 hi = __float2bfloat16(v);
        __nv_bfloat16 lo = __float2bfloat16(v - __bfloat162float(hi));
        size_t o = (size_t)nn * K + tk * 32 + c;
        Wh[o] = hi;
        Wl[o] = lo;
    }
}

// ---------------------------------------------------------------------------
// Projection GEMM 128x64, BK=32, double-buffered, split-K via gridDim.z.
// ---------------------------------------------------------------------------
#define GBM 128
#define GBN 64
#define GBK 32

template<int NSPLIT>
__global__ __launch_bounds__(256) void gemm_mma_kernel(
    const float* __restrict__ A, const __nv_bfloat16* __restrict__ Bhi,
    const __nv_bfloat16* __restrict__ Blo, const float* __restrict__ bias,
    float* __restrict__ C0, float* __restrict__ C1, int K)
{
    __shared__ __align__(1024) uint8_t sA[2][GBM * 128];
    __shared__ __align__(1024) uint8_t sB[2][GBN * 128];
    const uint32_t sAb0 = smem_u32(sA[0]), sAb1 = smem_u32(sA[1]);
    const uint32_t sBb0 = smem_u32(sB[0]), sBb1 = smem_u32(sB[1]);

    const int tid = threadIdx.x, wid = tid >> 5, lane = tid & 31;
    const int row0 = blockIdx.y * GBM;
    const int n0   = blockIdx.x * GBN;
    const int ksec  = K / NSPLIT;
    const int kbase = (NSPLIT > 1) ? blockIdx.z * ksec : 0;
    float* __restrict__ C = (NSPLIT > 1 && blockIdx.z == 1) ? C1 : C0;
    const int warpM = (wid >> 1) * 32;
    const int warpN = (wid & 1) * 32;

    float d[2][4][4];
#pragma unroll
    for (int mt = 0; mt < 2; mt++)
#pragma unroll
        for (int nt = 0; nt < 4; nt++)
#pragma unroll
            for (int i = 0; i < 4; i++) d[mt][nt][i] = 0.f;

    const int bn = tid >> 2, bq = tid & 3;
    const int NIT = ksec / GBK;
    float4 aR[4];

    auto ldgA = [&](int it) {
        const int k0 = kbase + it * GBK;
#pragma unroll
        for (int i = 0; i < 4; i++) {
            int slot = tid + i * 256;
            int r = slot >> 3, c = slot & 7;
            aR[i] = *reinterpret_cast<const float4*>(
                &A[(size_t)(row0 + r) * K + k0 + c * 4]);
        }
    };
    auto cpB = [&](int it, uint32_t sBb) {
        const int k0 = kbase + it * GBK;
        cp_async16(sBb + swz((uint32_t)(bn * 128 + bq * 16)),
                   &Bhi[(size_t)(n0 + bn) * K + k0 + bq * 8]);
        cp_async16(sBb + swz((uint32_t)(bn * 128 + 64 + bq * 16)),
                   &Blo[(size_t)(n0 + bn) * K + k0 + bq * 8]);
        cp_commit();
    };
    auto stsA = [&](uint8_t* dst) {
#pragma unroll
        for (int i = 0; i < 4; i++) {
            int slot = tid + i * 256;
            int r = slot >> 3, c = slot & 7;
            float4 v = aR[i];
            uint32_t h0 = pack_bf16(v.x, v.y), h1 = pack_bf16(v.z, v.w);
            float rx = v.x - __bfloat162float(__float2bfloat16(v.x));
            float ry = v.y - __bfloat162float(__float2bfloat16(v.y));
            float rz = v.z - __bfloat162float(__float2bfloat16(v.z));
            float rw = v.w - __bfloat162float(__float2bfloat16(v.w));
            uint32_t l0 = pack_bf16(rx, ry), l1 = pack_bf16(rz, rw);
            *reinterpret_cast<uint2*>(dst + swz((uint32_t)(r * 128 + c * 8)))
                = make_uint2(h0, h1);
            *reinterpret_cast<uint2*>(dst + swz((uint32_t)(r * 128 + 64 + c * 8)))
                = make_uint2(l0, l1);
        }
    };

    ldgA(0);
    cpB(0, sBb0);
    stsA(sA[0]);
    if (NIT > 1) ldgA(1);
    cp_wait0();
    __syncthreads();

    for (int it = 0; it < NIT; ++it) {
        const int s = it & 1;
        const uint32_t sAb = s ? sAb1 : sAb0;
        const uint32_t sBb = s ? sBb1 : sBb0;

        if (it + 1 < NIT) {
            cpB(it + 1, s ? sBb0 : sBb1);
            stsA(s ? sA[0] : sA[1]);
            if (it + 2 < NIT) ldgA(it + 2);
        }

#pragma unroll
        for (int kk = 0; kk < 2; kk++) {
            uint32_t ahi[2][4], alo[2][4], bhi[4][2], blo[4][2];
#pragma unroll
            for (int mt = 0; mt < 2; mt++) {
                int mrow = warpM + mt * 16 + (lane & 15);
                uint32_t kbyte = (uint32_t)((kk * 16 + ((lane >> 4) << 3)) * 2);
                ldm_x4(ahi[mt][0], ahi[mt][1], ahi[mt][2], ahi[mt][3],
                       sAb + swz((uint32_t)(mrow * 128) + kbyte));
                ldm_x4(alo[mt][0], alo[mt][1], alo[mt][2], alo[mt][3],
                       sAb + swz((uint32_t)(mrow * 128) + 64u + kbyte));
            }
#pragma unroll
            for (int p = 0; p < 2; p++) {
                int sel = lane >> 3, l8 = lane & 7;
                int nrow = warpN + p * 16 + ((sel & 2) ? 8 : 0) + l8;
                uint32_t kbyte = (uint32_t)((kk * 16 + (sel & 1) * 8) * 2);
                uint32_t q0, q1, q2, q3;
                ldm_x4(q0, q1, q2, q3, sBb + swz((uint32_t)(nrow * 128) + kbyte));
                bhi[p * 2 + 0][0] = q0; bhi[p * 2 + 0][1] = q1;
                bhi[p * 2 + 1][0] = q2; bhi[p * 2 + 1][1] = q3;
                ldm_x4(q0, q1, q2, q3, sBb + swz((uint32_t)(nrow * 128) + 64u + kbyte));
                blo[p * 2 + 0][0] = q0; blo[p * 2 + 0][1] = q1;
                blo[p * 2 + 1][0] = q2; blo[p * 2 + 1][1] = q3;
            }
#pragma unroll
            for (int mt = 0; mt < 2; mt++)
#pragma unroll
                for (int nt = 0; nt < 4; nt++) {
                    mma_bf16(d[mt][nt], ahi[mt], bhi[nt]);
                    mma_bf16(d[mt][nt], alo[mt], bhi[nt]);
                    mma_bf16(d[mt][nt], ahi[mt], blo[nt]);
                }
        }

        if (it + 1 < NIT) cp_wait0();
        __syncthreads();
    }

    const int rq = lane >> 2, cq = (lane & 3) * 2;
#pragma unroll
    for (int mt = 0; mt < 2; mt++)
#pragma unroll
        for (int nt = 0; nt < 4; nt++) {
            int row = row0 + warpM + mt * 16 + rq;
            int col = n0 + warpN + nt * 8 + cq;
            float b0 = 0.f, b1 = 0.f;
            if (NSPLIT == 1 && bias) { b0 = bias[col]; b1 = bias[col + 1]; }
            *reinterpret_cast<float2*>(&C[(size_t)row * HH + col]) =
                make_float2(d[mt][nt][0] + b0, d[mt][nt][1] + b1);
            *reinterpret_cast<float2*>(&C[(size_t)(row + 8) * HH + col]) =
                make_float2(d[mt][nt][2] + b0, d[mt][nt][3] + b1);
        }
}

// ---------------------------------------------------------------------------
// Small-GEMM (R10-verified): CTA tile 64x64, BK=32, double-buffered,
// 2 CTAs/SM (grid 256), 8 warps (4Mx2N, warp tile 16x32).
// ---------------------------------------------------------------------------
__global__ __launch_bounds__(256) void gemm_mma64_kernel(
    const float* __restrict__ A, const __nv_bfloat16* __restrict__ Bhi,
    const __nv_bfloat16* __restrict__ Blo,
    float* __restrict__ C, int K)
{
    __shared__ __align__(1024) uint8_t sA[2][64 * 128];   // 2 x 8 KB
    __shared__ __align__(1024) uint8_t sB[2][64 * 128];   // 2 x 8 KB
    const uint32_t sAb0 = smem_u32(sA[0]), sAb1 = smem_u32(sA[1]);
    const uint32_t sBb0 = smem_u32(sB[0]), sBb1 = smem_u32(sB[1]);

    const int tid = threadIdx.x, wid = tid >> 5, lane = tid & 31;
    const int row0 = blockIdx.y * 64;
    const int n0   = blockIdx.x * 64;
    const int warpM = (wid >> 1) * 16;
    const int warpN = (wid & 1) * 32;

    float d[4][4];
#pragma unroll
    for (int nt = 0; nt < 4; nt++)
#pragma unroll
        for (int i = 0; i < 4; i++) d[nt][i] = 0.f;

    const int bn = tid >> 2, bq = tid & 3;
    const int NIT = K / GBK;
    float4 aR[2];

    auto ldgA = [&](int it) {
        const int k0 = it * GBK;
#pragma unroll
        for (int i = 0; i < 2; i++) {
            int slot = tid + i * 256;
            int r = slot >> 3, c = slot & 7;
            aR[i] = *reinterpret_cast<const float4*>(
                &A[(size_t)(row0 + r) * K + k0 + c * 4]);
        }
    };
    auto cpB = [&](int it, uint32_t sBb) {
        const int k0 = it * GBK;
        cp_async16(sBb + swz((uint32_t)(bn * 128 + bq * 16)),
                   &Bhi[(size_t)(n0 + bn) * K + k0 + bq * 8]);
        cp_async16(sBb + swz((uint32_t)(bn * 128 + 64 + bq * 16)),
                   &Blo[(size_t)(n0 + bn) * K + k0 + bq * 8]);
        cp_commit();
    };
    auto stsA = [&](uint8_t* dst) {
#pragma unroll
        for (int i = 0; i < 2; i++) {
            int slot = tid + i * 256;
            int r = slot >> 3, c = slot & 7;
            float4 v = aR[i];
            uint32_t h0 = pack_bf16(v.x, v.y), h1 = pack_bf16(v.z, v.w);
            float rx = v.x - __bfloat162float(__float2bfloat16(v.x));
            float ry = v.y - __bfloat162float(__float2bfloat16(v.y));
            float rz = v.z - __bfloat162float(__float2bfloat16(v.z));
            float rw = v.w - __bfloat162float(__float2bfloat16(v.w));
            uint32_t l0 = pack_bf16(rx, ry), l1 = pack_bf16(rz, rw);
            *reinterpret_cast<uint2*>(dst + swz((uint32_t)(r * 128 + c * 8)))
                = make_uint2(h0, h1);
            *reinterpret_cast<uint2*>(dst + swz((uint32_t)(r * 128 + 64 + c * 8)))
                = make_uint2(l0, l1);
        }
    };

    ldgA(0);
    cpB(0, sBb0);
    stsA(sA[0]);
    if (NIT > 1) ldgA(1);
    cp_wait0();
    __syncthreads();

    for (int it = 0; it < NIT; ++it) {
        const int s = it & 1;
        const uint32_t sAb = s ? sAb1 : sAb0;
        const uint32_t sBb = s ? sBb1 : sBb0;

        if (it + 1 < NIT) {
            cpB(it + 1, s ? sBb0 : sBb1);
            stsA(s ? sA[0] : sA[1]);
            if (it + 2 < NIT) ldgA(it + 2);
        }

#pragma unroll
        for (int kk = 0; kk < 2; kk++) {
            uint32_t ahi[4], alo[4], bhi[4][2], blo[4][2];
            {
                int mrow = warpM + (lane & 15);
                uint32_t kbyte = (uint32_t)((kk * 16 + ((lane >> 4) << 3)) * 2);
                ldm_x4(ahi[0], ahi[1], ahi[2], ahi[3],
                       sAb + swz((uint32_t)(mrow * 128) + kbyte));
                ldm_x4(alo[0], alo[1], alo[2], alo[3],
                       sAb + swz((uint32_t)(mrow * 128) + 64u + kbyte));
            }
#pragma unroll
            for (int p = 0; p < 2; p++) {
                int sel = lane >> 3, l8 = lane & 7;
                int nrow = warpN + p * 16 + ((sel & 2) ? 8 : 0) + l8;
                uint32_t kbyte = (uint32_t)((kk * 16 + (sel & 1) * 8) * 2);
                uint32_t q0, q1, q2, q3;
                ldm_x4(q0, q1, q2, q3, sBb + swz((uint32_t)(nrow * 128) + kbyte));
                bhi[p * 2 + 0][0] = q0; bhi[p * 2 + 0][1] = q1;
                bhi[p * 2 + 1][0] = q2; bhi[p * 2 + 1][1] = q3;
                ldm_x4(q0, q1, q2, q3, sBb + swz((uint32_t)(nrow * 128) + 64u + kbyte));
                blo[p * 2 + 0][0] = q0; blo[p * 2 + 0][1] = q1;
                blo[p * 2 + 1][0] = q2; blo[p * 2 + 1][1] = q3;
            }
#pragma unroll
            for (int nt = 0; nt < 4; nt++) {
                mma_bf16(d[nt], ahi, bhi[nt]);
                mma_bf16(d[nt], alo, bhi[nt]);
                mma_bf16(d[nt], ahi, blo[nt]);
            }
        }

        if (it + 1 < NIT) cp_wait0();
        __syncthreads();
    }

    const int rq = lane >> 2, cq = (lane & 3) * 2;
#pragma unroll
    for (int nt = 0; nt < 4; nt++) {
        int row = row0 + warpM + rq;
        int col = n0 + warpN + nt * 8 + cq;
        *reinterpret_cast<float2*>(&C[(size_t)row * HH + col]) =
            make_float2(d[nt][0], d[nt][1]);
        *reinterpret_cast<float2*>(&C[(size_t)(row + 8) * HH + col]) =
            make_float2(d[nt][2], d[nt][3]);
    }
}

// ---------------------------------------------------------------------------
// Split-K reduction: C = P0 + P1 + bias
// ---------------------------------------------------------------------------
__global__ __launch_bounds__(256) void addbias_kernel(
    const float* __restrict__ P0, const float* __restrict__ P1,
    const float* __restrict__ bias, float* __restrict__ C)
{
    int i = blockIdx.x * 256 + threadIdx.x;
    int col = (i * 4) & (HH - 1);
    float4 a = *reinterpret_cast<const float4*>(&P0[(size_t)i * 4]);
    float4 b = *reinterpret_cast<const float4*>(&P1[(size_t)i * 4]);
    float4 bv = *reinterpret_cast<const float4*>(&bias[col]);
    *reinterpret_cast<float4*>(&C[(size_t)i * 4]) =
        make_float4(a.x + b.x + bv.x, a.y + b.y + bv.y,
                    a.z + b.z + bv.z, a.w + b.w + bv.w);
}

// ---------------------------------------------------------------------------
// Fused attention: RPB=16, zero-padded tile, JOINT 2-row register aggregation,
// + residual + LN (+ final LN). 2 CTAs/SM.
// ---------------------------------------------------------------------------
#define RPB   16
#define NTROW (RPB + 2*WINR)              // 46
#define NJ    (2*WINR + 1)                // 31
#define WST   33
#define AT_TILE 0
#define AT_ES   47104
#define AT_ED   47872
#define AT_SA   48640
#define AT_SD   49664
#define AT_W    50688
#define ATTN_SMEM 59136

template<bool FINAL_LN>
__global__ __launch_bounds__(256, 2) void attn_fused_kernel(
    const float* __restrict__ h,  const float* __restrict__ hW,
    const float* __restrict__ asrc, const float* __restrict__ adst,
    const float* __restrict__ g,  const float* __restrict__ b,
    const float* __restrict__ gF, const float* __restrict__ bF,
    float* __restrict__ out)
{
    extern __shared__ char sm[];
    float* tile = (float*)(sm + AT_TILE);
    float* es_s = (float*)(sm + AT_ES);
    float* ed_s = (float*)(sm + AT_ED);
    float* sa   = (float*)(sm + AT_SA);
    float* sd   = (float*)(sm + AT_SD);
    float* wsm  = (float*)(sm + AT_W);

    const int tid = threadIdx.x, wid = tid >> 5, lane = tid & 31;
    const int bpb = TT / RPB;
    const int batch = blockIdx.x / bpb;
    const int t0 = (blockIdx.x - batch * bpb) * RPB;
    const int gbase = batch * TT;

    for (int idx = tid; idx < NTROW * 64; idx += 256) {
        int r = idx >> 6, c4 = idx & 63;
        int tg = t0 - WINR + r;
        float4 v = make_float4(0.f, 0.f, 0.f, 0.f);
        if (tg >= 0 && tg < TT)
            v = *reinterpret_cast<const float4*>(
                &hW[(size_t)(gbase + tg) * HH + c4 * 4]);
        *reinterpret_cast<float4*>(&tile[r * 256 + c4 * 4]) = v;
    }
    sa[tid] = asrc[tid];
    sd[tid] = adst[tid];
    __syncthreads();

    {
        const int head = lane >> 3, dk = lane & 7;
        const int base4 = head * 16 + dk * 2;
        float4 s0 = *reinterpret_cast<float4*>(&sa[base4 * 4]);
        float4 s1 = *reinterpret_cast<float4*>(&sa[base4 * 4 + 4]);
        float4 dd0 = *reinterpret_cast<float4*>(&sd[base4 * 4]);
        float4 dd1 = *reinterpret_cast<float4*>(&sd[base4 * 4 + 4]);
        for (int r = wid; r < NTROW; r += 8) {
            float4 v0 = *reinterpret_cast<float4*>(&tile[r * 256 + base4 * 4]);
            float4 v1 = *reinterpret_cast<float4*>(&tile[r * 256 + base4 * 4 + 4]);
            float ps = v0.x*s0.x + v0.y*s0.y + v0.z*s0.z + v0.w*s0.w
                     + v1.x*s1.x + v1.y*s1.y + v1.z*s1.z + v1.w*s1.w;
            float pd = v0.x*dd0.x + v0.y*dd0.y + v0.z*dd0.z + v0.w*dd0.w
                     + v1.x*dd1.x + v1.y*dd1.y + v1.z*dd1.z + v1.w*dd1.w;
#pragma unroll
            for (int o = 4; o > 0; o >>= 1) {
                ps += __shfl_xor_sync(0xffffffffu, ps, o);
                pd += __shfl_xor_sync(0xffffffffu, pd, o);
            }
            if (dk == 0) { es_s[r * 4 + head] = ps; ed_s[r * 4 + head] = pd; }
        }
    }
    __syncthreads();

#pragma unroll
    for (int q = 0; q < 8; q++) {
        int p = wid + 8 * q;
        int r = p >> 2, head = p & 3;
        int t = t0 + r;
        int tn = t - WINR + lane;
        bool valid = (lane < NJ) && (tn >= 0) && (tn < TT);
        float e = -1e30f;
        if (valid) {
            float v = es_s[(r + WINR) * 4 + head] + ed_s[(r + lane) * 4 + head];
            e = (v > 0.f) ? v : 0.2f * v;
        }
        float m = e;
#pragma unroll
        for (int o = 16; o > 0; o >>= 1) m = fmaxf(m, __shfl_xor_sync(0xffffffffu, m, o));
        float xv = valid ? __expf(e - m) : 0.f;
        float s = xv;
#pragma unroll
        for (int o = 16; o > 0; o >>= 1) s += __shfl_xor_sync(0xffffffffu, s, o);
        wsm[p * WST + lane] = xv / s;    // lane 31 stores exactly 0
    }
    __syncthreads();

    // --- joint 2-row aggregation: rows r0=2*wid, r0+1 share tile rows ---
    const int c0 = lane * 8;
    const int head = lane >> 3;
    const int r0 = wid * 2;
    const float* w0 = &wsm[(r0 * 4 + head) * WST];
    const float* w1 = &wsm[((r0 + 1) * 4 + head) * WST];
    float a0[8], a1[8];
#pragma unroll
    for (int k = 0; k < 8; k++) { a0[k] = 0.f; a1[k] = 0.f; }
#pragma unroll
    for (int u = 0; u < 32; u++) {
        const float* trow = &tile[(r0 + u) * 256 + c0];
        float4 t0v = *reinterpret_cast<const float4*>(trow);
        float4 t1v = *reinterpret_cast<const float4*>(trow + 4);
        float wa = w0[u];                         // w0[31] == 0
        float wb = (u == 0) ? 0.f : w1[u - 1];
        a0[0] = fmaf(wa, t0v.x, a0[0]); a0[1] = fmaf(wa, t0v.y, a0[1]);
        a0[2] = fmaf(wa, t0v.z, a0[2]); a0[3] = fmaf(wa, t0v.w, a0[3]);
        a0[4] = fmaf(wa, t1v.x, a0[4]); a0[5] = fmaf(wa, t1v.y, a0[5]);
        a0[6] = fmaf(wa, t1v.z, a0[6]); a0[7] = fmaf(wa, t1v.w, a0[7]);
        a1[0] = fmaf(wb, t0v.x, a1[0]); a1[1] = fmaf(wb, t0v.y, a1[1]);
        a1[2] = fmaf(wb, t0v.z, a1[2]); a1[3] = fmaf(wb, t0v.w, a1[3]);
        a1[4] = fmaf(wb, t1v.x, a1[4]); a1[5] = fmaf(wb, t1v.y, a1[5]);
        a1[6] = fmaf(wb, t1v.z, a1[6]); a1[7] = fmaf(wb, t1v.w, a1[7]);
    }

    // --- per-row residual + LN (+ final LN) + store ---
#pragma unroll
    for (int rr = 0; rr < 2; rr++) {
        float* a = rr ? a1 : a0;
        const int r = r0 + rr;
        const size_t grow = (size_t)(gbase + t0 + r) * HH;
        float4 h0v = *reinterpret_cast<const float4*>(&h[grow + c0]);
        float4 h1v = *reinterpret_cast<const float4*>(&h[grow + c0 + 4]);
        a[0] += h0v.x; a[1] += h0v.y; a[2] += h0v.z; a[3] += h0v.w;
        a[4] += h1v.x; a[5] += h1v.y; a[6] += h1v.z; a[7] += h1v.w;
        float s1 = 0.f, s2 = 0.f;
#pragma unroll
        for (int k = 0; k < 8; k++) { s1 += a[k]; s2 += a[k] * a[k]; }
#pragma unroll
        for (int o = 16; o > 0; o >>= 1) {
            s1 += __shfl_xor_sync(0xffffffffu, s1, o);
            s2 += __shfl_xor_sync(0xffffffffu, s2, o);
        }
        float mu  = s1 * (1.f / 256.f);
        float var = s2 * (1.f / 256.f) - mu * mu;
        float inv = rsqrtf(var + EPSV);
        float4 g0v = *reinterpret_cast<const float4*>(&g[c0]);
        float4 g1v = *reinterpret_cast<const float4*>(&g[c0 + 4]);
        float4 b0v = *reinterpret_cast<const float4*>(&b[c0]);
        float4 b1v = *reinterpret_cast<const float4*>(&b[c0 + 4]);
        float z[8];
        z[0] = (a[0]-mu)*inv*g0v.x + b0v.x; z[1] = (a[1]-mu)*inv*g0v.y + b0v.y;
        z[2] = (a[2]-mu)*inv*g0v.z + b0v.z; z[3] = (a[3]-mu)*inv*g0v.w + b0v.w;
        z[4] = (a[4]-mu)*inv*g1v.x + b1v.x; z[5] = (a[5]-mu)*inv*g1v.y + b1v.y;
        z[6] = (a[6]-mu)*inv*g1v.z + b1v.z; z[7] = (a[7]-mu)*inv*g1v.w + b1v.w;
        if (FINAL_LN) {
            float z1 = 0.f, z2 = 0.f;
#pragma unroll
            for (int k = 0; k < 8; k++) { z1 += z[k]; z2 += z[k] * z[k]; }
#pragma unroll
            for (int o = 16; o > 0; o >>= 1) {
                z1 += __shfl_xor_sync(0xffffffffu, z1, o);
                z2 += __shfl_xor_sync(0xffffffffu, z2, o);
            }
            float mu2  = z1 * (1.f / 256.f);
            float var2 = z2 * (1.f / 256.f) - mu2 * mu2;
            float inv2 = rsqrtf(var2 + EPSV);
            float4 gf0 = *reinterpret_cast<const float4*>(&gF[c0]);
            float4 gf1 = *reinterpret_cast<const float4*>(&gF[c0 + 4]);
            float4 bf0 = *reinterpret_cast<const float4*>(&bF[c0]);
            float4 bf1 = *reinterpret_cast<const float4*>(&bF[c0 + 4]);
            z[0] = (z[0]-mu2)*inv2*gf0.x + bf0.x; z[1] = (z[1]-mu2)*inv2*gf0.y + bf0.y;
            z[2] = (z[2]-mu2)*inv2*gf0.z + bf0.z; z[3] = (z[3]-mu2)*inv2*gf0.w + bf0.w;
            z[4] = (z[4]-mu2)*inv2*gf1.x + bf1.x; z[5] = (z[5]-mu2)*inv2*gf1.y + bf1.y;
            z[6] = (z[6]-mu2)*inv2*gf1.z + bf1.z; z[7] = (z[7]-mu2)*inv2*gf1.w + bf1.w;
        }
        *reinterpret_cast<float4*>(&out[grow + c0]) =
            make_float4(z[0], z[1], z[2], z[3]);
        *reinterpret_cast<float4*>(&out[grow + c0 + 4]) =
            make_float4(z[4], z[5], z[6], z[7]);
    }
}

// ---------------------------------------------------------------------------
extern "C" void kernel_launch(void* const* d_in, const int* in_sizes, int n_in,
                              void* d_out, int out_size)
{
    const float* x     = (const float*)d_in[0];
    // d_in[1] = adj_mask (banded window reconstructed analytically; unused)
    const float* Wp    = (const float*)d_in[2];
    const float* bp    = (const float*)d_in[3];
    const float* W0    = (const float*)d_in[4];
    const float* asrc0 = (const float*)d_in[5];
    const float* adst0 = (const float*)d_in[6];
    const float* g0    = (const float*)d_in[7];
    const float* b0    = (const float*)d_in[8];
    const float* W1    = (const float*)d_in[9];
    const float* asrc1 = (const float*)d_in[10];
    const float* adst1 = (const float*)d_in[11];
    const float* g1    = (const float*)d_in[12];
    const float* b1    = (const float*)d_in[13];
    const float* gF    = (const float*)d_in[14];
    const float* bF    = (const float*)d_in[15];
    float* out = (float*)d_out;

    float *h0, *h1, *hW;
    __nv_bfloat16 *Wpth, *Wptl, *W0th, *W0tl, *W1th, *W1tl;
    cudaGetSymbolAddress((void**)&h0, g_h0);
    cudaGetSymbolAddress((void**)&h1, g_h1);
    cudaGetSymbolAddress((void**)&hW, g_hW);
    cudaGetSymbolAddress((void**)&Wpth, g_Wpt_hi);
    cudaGetSymbolAddress((void**)&Wptl, g_Wpt_lo);
    cudaGetSymbolAddress((void**)&W0th, g_W0t_hi);
    cudaGetSymbolAddress((void**)&W0tl, g_W0t_lo);
    cudaGetSymbolAddress((void**)&W1th, g_W1t_hi);
    cudaGetSymbolAddress((void**)&W1tl, g_W1t_lo);

    cudaFuncSetAttribute(attn_fused_kernel<false>,
        cudaFuncAttributeMaxDynamicSharedMemorySize, ATTN_SMEM);
    cudaFuncSetAttribute(attn_fused_kernel<true>,
        cudaFuncAttributeMaxDynamicSharedMemorySize, ATTN_SMEM);

    // Weight prep: tiled transpose, 640 blocks
    wprep_tiled_kernel<<<640, 256>>>(
        Wp, Wpth, Wptl, W0, W0th, W0tl, W1, W1th, W1tl);

    // ---- projection: split-K=2 partials + reduce ----
    dim3 gProj(HH / GBN, BT / GBM, 2);      // (4, 32, 2) = 256 CTAs
    gemm_mma_kernel<2><<<gProj, 256>>>(x, Wpth, Wptl, nullptr, h1, hW, DD);
    addbias_kernel<<<(BT * HH / 4) / 256, 256>>>(h1, hW, bp, h0);

    dim3 gg64(HH / 64, BT / 64);            // (4, 64) = 256 CTAs

    // --- GAT block 0 ---
    gemm_mma64_kernel<<<gg64, 256>>>(h0, W0th, W0tl, hW, HH);
    attn_fused_kernel<false><<<BT / RPB, 256, ATTN_SMEM>>>(
        h0, hW, asrc0, adst0, g0, b0, nullptr, nullptr, h1);

    // --- GAT block 1 (final LN fused, writes d_out) ---
    gemm_mma64_kernel<<<gg64, 256>>>(h1, W1th, W1tl, hW, HH);
    attn_fused_kernel<true><<<BT / RPB, 256, ATTN_SMEM>>>(
        h1, hW, asrc1, adst1, g1, b1, gF, bF, out);
}